// round 4
// baseline (speedup 1.0000x reference)
#include <cuda_runtime.h>
#include <math.h>

#define NB 64
#define NT 512
#define NF 512
#define NDIN 1024
#define NH 1024
#define NZ 4096
#define NDOUT 128
#define SH (NB*NH)     // 65536 state elements per buffer
#define NBLK 128       // persistent blocks (<= 148 SMs, all co-resident)

// Scratch (device globals; no dynamic allocation allowed)
__device__ float g_xin[(size_t)NT * NB * NDIN];   // tanh(x@Wi+bi), rows r = t*NB+b
__device__ float g_P0[(size_t)NT * NB * NZ];      // xin@W0 + b0
__device__ float g_h0[2 * SH];                    // double-buffered hidden states
__device__ float g_h1[2 * SH];

// grid barrier state
__device__ unsigned g_count;
__device__ volatile unsigned g_gen;

// ---------------------------------------------------------------------------
__global__ void k_init() {
    int idx = blockIdx.x * blockDim.x + threadIdx.x;
    if (idx < 2 * SH) { g_h0[idx] = 0.f; g_h1[idx] = 0.f; }
    if (idx == 0) { g_count = 0; g_gen = 0; }
}

// ---------------------------------------------------------------------------
// k_xin: xin[r, n] = tanh( x[b,t,:] @ Wi[:,n] + bi[n] ),  r = t*NB + b
// GEMM M=32768, K=512, N=1024. Tile 64x64, 256 threads, 4x4 per thread.
// ---------------------------------------------------------------------------
__global__ __launch_bounds__(256) void k_xin(const float* __restrict__ x,
                                             const float* __restrict__ Wi,
                                             const float* __restrict__ bi) {
    __shared__ float As[16][64];
    __shared__ float Bs[16][64];
    int tid = threadIdx.x;
    int tx = tid & 15, ty = tid >> 4;
    int n0 = blockIdx.x * 64;
    int row0 = blockIdx.y * 64;

    float acc[4][4] = {};

    int ar = tid & 63, akq = tid >> 6;
    int R = row0 + ar;
    int bb = R & 63, tt = R >> 6;               // r = t*NB + b
    const float* aptr = x + ((size_t)bb * NT + tt) * NF + akq * 4;
    int bkk = tid >> 4, bnq = tid & 15;
    const float* bptr = Wi + (size_t)bkk * NDIN + n0 + bnq * 4;

    float4 pa = *(const float4*)aptr;
    float4 pb = *(const float4*)bptr;

    const int NC = NF / 16;
    for (int c = 0; c < NC; c++) {
        As[akq * 4 + 0][ar] = pa.x; As[akq * 4 + 1][ar] = pa.y;
        As[akq * 4 + 2][ar] = pa.z; As[akq * 4 + 3][ar] = pa.w;
        *(float4*)&Bs[bkk][bnq * 4] = pb;
        __syncthreads();
        if (c + 1 < NC) {
            pa = *(const float4*)(aptr + (c + 1) * 16);
            pb = *(const float4*)(bptr + (size_t)(c + 1) * 16 * NDIN);
        }
#pragma unroll
        for (int kk = 0; kk < 16; kk++) {
            float4 a = *(const float4*)&As[kk][ty * 4];
            float4 b = *(const float4*)&Bs[kk][tx * 4];
            acc[0][0] += a.x * b.x; acc[0][1] += a.x * b.y; acc[0][2] += a.x * b.z; acc[0][3] += a.x * b.w;
            acc[1][0] += a.y * b.x; acc[1][1] += a.y * b.y; acc[1][2] += a.y * b.z; acc[1][3] += a.y * b.w;
            acc[2][0] += a.z * b.x; acc[2][1] += a.z * b.y; acc[2][2] += a.z * b.z; acc[2][3] += a.z * b.w;
            acc[3][0] += a.w * b.x; acc[3][1] += a.w * b.y; acc[3][2] += a.w * b.z; acc[3][3] += a.w * b.w;
        }
        __syncthreads();
    }
#pragma unroll
    for (int i = 0; i < 4; i++) {
        int r = row0 + ty * 4 + i;
#pragma unroll
        for (int jx = 0; jx < 4; jx++) {
            int n = n0 + tx * 4 + jx;
            g_xin[(size_t)r * NDIN + n] = tanhf(acc[i][jx] + bi[n]);
        }
    }
}

// ---------------------------------------------------------------------------
// k_p0: P0 = xin @ W0 + b0.  GEMM M=32768, K=1024, N=4096.
// Tile 128x64, 256 threads, 8x4 per thread.
// ---------------------------------------------------------------------------
__global__ __launch_bounds__(256) void k_p0(const float* __restrict__ W0,
                                            const float* __restrict__ b0) {
    __shared__ float As[16][128];
    __shared__ float Bs[16][64];
    int tid = threadIdx.x;
    int tx = tid & 15, ty = tid >> 4;
    int n0 = blockIdx.x * 64;
    int row0 = blockIdx.y * 128;

    float acc[8][4] = {};

    int ar = tid & 127, akq0 = tid >> 7;
    const float* aptr0 = g_xin + (size_t)(row0 + ar) * NDIN + akq0 * 4;
    const float* aptr1 = g_xin + (size_t)(row0 + ar) * NDIN + (akq0 + 2) * 4;
    int bkk = tid >> 4, bnq = tid & 15;
    const float* bptr = W0 + (size_t)bkk * NZ + n0 + bnq * 4;

    float4 pa0 = *(const float4*)aptr0;
    float4 pa1 = *(const float4*)aptr1;
    float4 pb  = *(const float4*)bptr;

    const int NC = NDIN / 16;
    for (int c = 0; c < NC; c++) {
        As[akq0 * 4 + 0][ar] = pa0.x; As[akq0 * 4 + 1][ar] = pa0.y;
        As[akq0 * 4 + 2][ar] = pa0.z; As[akq0 * 4 + 3][ar] = pa0.w;
        As[(akq0 + 2) * 4 + 0][ar] = pa1.x; As[(akq0 + 2) * 4 + 1][ar] = pa1.y;
        As[(akq0 + 2) * 4 + 2][ar] = pa1.z; As[(akq0 + 2) * 4 + 3][ar] = pa1.w;
        *(float4*)&Bs[bkk][bnq * 4] = pb;
        __syncthreads();
        if (c + 1 < NC) {
            pa0 = *(const float4*)(aptr0 + (c + 1) * 16);
            pa1 = *(const float4*)(aptr1 + (c + 1) * 16);
            pb  = *(const float4*)(bptr + (size_t)(c + 1) * 16 * NZ);
        }
#pragma unroll
        for (int kk = 0; kk < 16; kk++) {
            float4 a0 = *(const float4*)&As[kk][ty * 8];
            float4 a1 = *(const float4*)&As[kk][ty * 8 + 4];
            float4 b  = *(const float4*)&Bs[kk][tx * 4];
            acc[0][0] += a0.x * b.x; acc[0][1] += a0.x * b.y; acc[0][2] += a0.x * b.z; acc[0][3] += a0.x * b.w;
            acc[1][0] += a0.y * b.x; acc[1][1] += a0.y * b.y; acc[1][2] += a0.y * b.z; acc[1][3] += a0.y * b.w;
            acc[2][0] += a0.z * b.x; acc[2][1] += a0.z * b.y; acc[2][2] += a0.z * b.z; acc[2][3] += a0.z * b.w;
            acc[3][0] += a0.w * b.x; acc[3][1] += a0.w * b.y; acc[3][2] += a0.w * b.z; acc[3][3] += a0.w * b.w;
            acc[4][0] += a1.x * b.x; acc[4][1] += a1.x * b.y; acc[4][2] += a1.x * b.z; acc[4][3] += a1.x * b.w;
            acc[5][0] += a1.y * b.x; acc[5][1] += a1.y * b.y; acc[5][2] += a1.y * b.z; acc[5][3] += a1.y * b.w;
            acc[6][0] += a1.z * b.x; acc[6][1] += a1.z * b.y; acc[6][2] += a1.z * b.z; acc[6][3] += a1.z * b.w;
            acc[7][0] += a1.w * b.x; acc[7][1] += a1.w * b.y; acc[7][2] += a1.w * b.z; acc[7][3] += a1.w * b.w;
        }
        __syncthreads();
    }
#pragma unroll
    for (int i = 0; i < 8; i++) {
        int r = row0 + ty * 8 + i;
#pragma unroll
        for (int jx = 0; jx < 4; jx++) {
            int n = n0 + tx * 4 + jx;
            g_P0[(size_t)r * NZ + n] = acc[i][jx] + b0[n];
        }
    }
}

__device__ __forceinline__ float sigmoidf_(float v) {
    return 1.f / (1.f + __expf(-v));
}

// ---------------------------------------------------------------------------
// software grid barrier (all NBLK blocks co-resident)
// ---------------------------------------------------------------------------
__device__ __forceinline__ void grid_sync_() {
    __syncthreads();
    if (threadIdx.x == 0) {
        __threadfence();
        unsigned gen = g_gen;
        if (atomicAdd(&g_count, 1u) == NBLK - 1) {
            g_count = 0;
            __threadfence();
            g_gen = gen + 1;
        } else {
            while (g_gen == gen) { }
        }
        __threadfence();
    }
    __syncthreads();
}

// ---------------------------------------------------------------------------
// k_rnn: entire 512-step recurrence in ONE persistent kernel.
// 128 blocks x 256 threads. Block owns j-strip of 8 hidden units x 4 gates.
// Thread (jj = tid&7, tr = tid>>3) computes 2 rows x 4 gates -> 2 (row,j)
// cells per layer; c-state lives in registers across all timesteps.
// ---------------------------------------------------------------------------
__global__ __launch_bounds__(256) void k_rnn(const float* __restrict__ U0,
                                             const float* __restrict__ W1,
                                             const float* __restrict__ U1,
                                             const float* __restrict__ b1) {
    __shared__ float As[16][64];   // [kk][row]
    __shared__ float Bs[16][32];   // [kk][jj*4 + gate]
    int tid = threadIdx.x;
    int jj = tid & 7, tr = tid >> 3;
    int j0 = blockIdx.x * 8;
    int j = j0 + jj;

    int ar = tid & 63, akq = tid >> 6;
    int e1 = tid + 256;
    int bjj0 = tid & 7, bg0 = (tid >> 3) & 3, bkk0 = tid >> 5;
    int bjj1 = e1 & 7, bg1 = (e1 >> 3) & 3, bkk1 = e1 >> 5;
    size_t bOff0 = (size_t)bkk0 * NZ + (size_t)bg0 * NH + j0 + bjj0;
    size_t bOff1 = (size_t)bkk1 * NZ + (size_t)bg1 * NH + j0 + bjj1;

    float c0reg[2] = {0.f, 0.f};
    float c1reg[2] = {0.f, 0.f};
    float b1g0 = b1[j], b1g1 = b1[NH + j], b1g2 = b1[2 * NH + j], b1g3 = b1[3 * NH + j];

    for (int t = 0; t < NT; t++) {
        const float* h0r = g_h0 + (size_t)(t & 1) * SH;
        float*       h0w = g_h0 + (size_t)((t & 1) ^ 1) * SH;
        const float* h1r = g_h1 + (size_t)(t & 1) * SH;
        float*       h1w = g_h1 + (size_t)((t & 1) ^ 1) * SH;

        // ================= phase A: z0 = P0[t] + h0r @ U0 =================
        {
            float acc[2][4] = {};
            const float* aptr = h0r + (size_t)ar * NH + akq * 4;
            float4 pa = *(const float4*)aptr;
            float pb0 = U0[bOff0];
            float pb1 = U0[bOff1];
            const int NC = NH / 16;
            for (int c = 0; c < NC; c++) {
                As[akq * 4 + 0][ar] = pa.x; As[akq * 4 + 1][ar] = pa.y;
                As[akq * 4 + 2][ar] = pa.z; As[akq * 4 + 3][ar] = pa.w;
                Bs[bkk0][bjj0 * 4 + bg0] = pb0;
                Bs[bkk1][bjj1 * 4 + bg1] = pb1;
                __syncthreads();
                if (c + 1 < NC) {
                    pa  = *(const float4*)(aptr + (c + 1) * 16);
                    pb0 = U0[bOff0 + (size_t)(c + 1) * 16 * NZ];
                    pb1 = U0[bOff1 + (size_t)(c + 1) * 16 * NZ];
                }
#pragma unroll
                for (int kk = 0; kk < 16; kk++) {
                    float2 a = *(const float2*)&As[kk][tr * 2];
                    float4 b = *(const float4*)&Bs[kk][jj * 4];
                    acc[0][0] += a.x * b.x; acc[0][1] += a.x * b.y; acc[0][2] += a.x * b.z; acc[0][3] += a.x * b.w;
                    acc[1][0] += a.y * b.x; acc[1][1] += a.y * b.y; acc[1][2] += a.y * b.z; acc[1][3] += a.y * b.w;
                }
                __syncthreads();
            }
#pragma unroll
            for (int rr = 0; rr < 2; rr++) {
                int row = tr * 2 + rr;
                size_t pbase = ((size_t)t * NB + row) * NZ;
                float zi = acc[rr][0] + g_P0[pbase + j];
                float zf = acc[rr][1] + g_P0[pbase + NH + j];
                float zc = acc[rr][2] + g_P0[pbase + 2 * NH + j];
                float zo = acc[rr][3] + g_P0[pbase + 3 * NH + j];
                float cv = sigmoidf_(zf) * c0reg[rr] + sigmoidf_(zi) * tanhf(zc);
                c0reg[rr] = cv;
                h0w[row * NH + j] = sigmoidf_(zo) * tanhf(cv);
            }
        }
        grid_sync_();

        // ========== phase B: z1 = h0w @ W1 + h1r @ U1 + b1 (K=2048) ==========
        {
            float acc[2][4] = {};
            float4 pa = *(const float4*)(h0w + (size_t)ar * NH + akq * 4);
            float pb0 = W1[bOff0];
            float pb1 = W1[bOff1];
            const int NC = (2 * NH) / 16;
            for (int c = 0; c < NC; c++) {
                As[akq * 4 + 0][ar] = pa.x; As[akq * 4 + 1][ar] = pa.y;
                As[akq * 4 + 2][ar] = pa.z; As[akq * 4 + 3][ar] = pa.w;
                Bs[bkk0][bjj0 * 4 + bg0] = pb0;
                Bs[bkk1][bjj1 * 4 + bg1] = pb1;
                __syncthreads();
                if (c + 1 < NC) {
                    int k0n = (c + 1) * 16;
                    const float* srcA = (k0n < NH) ? h0w : h1r;
                    const float* srcB = (k0n < NH) ? W1 : U1;
                    int koff = (k0n < NH) ? k0n : (k0n - NH);
                    pa  = *(const float4*)(srcA + (size_t)ar * NH + koff + akq * 4);
                    pb0 = srcB[bOff0 + (size_t)koff * NZ];
                    pb1 = srcB[bOff1 + (size_t)koff * NZ];
                }
#pragma unroll
                for (int kk = 0; kk < 16; kk++) {
                    float2 a = *(const float2*)&As[kk][tr * 2];
                    float4 b = *(const float4*)&Bs[kk][jj * 4];
                    acc[0][0] += a.x * b.x; acc[0][1] += a.x * b.y; acc[0][2] += a.x * b.z; acc[0][3] += a.x * b.w;
                    acc[1][0] += a.y * b.x; acc[1][1] += a.y * b.y; acc[1][2] += a.y * b.z; acc[1][3] += a.y * b.w;
                }
                __syncthreads();
            }
#pragma unroll
            for (int rr = 0; rr < 2; rr++) {
                int row = tr * 2 + rr;
                float zi = acc[rr][0] + b1g0;
                float zf = acc[rr][1] + b1g1;
                float zc = acc[rr][2] + b1g2;
                float zo = acc[rr][3] + b1g3;
                float cv = sigmoidf_(zf) * c1reg[rr] + sigmoidf_(zi) * tanhf(zc);
                c1reg[rr] = cv;
                h1w[row * NH + j] = sigmoidf_(zo) * tanhf(cv);
            }
        }
        grid_sync_();
    }
}

// ---------------------------------------------------------------------------
// k_out: out = tanh( h1_final @ Wo + bo ),  [64,1024]@[1024,128]
// ---------------------------------------------------------------------------
__global__ void k_out(const float* __restrict__ Wo, const float* __restrict__ bo,
                      float* __restrict__ out) {
    int idx = blockIdx.x * blockDim.x + threadIdx.x;
    if (idx >= NB * NDOUT) return;
    int n = idx & 127, b = idx >> 7;
    const float* h = g_h1;   // final h1 lives in parity-0 buffer after T=512 steps
    float s0 = 0.f, s1 = 0.f, s2 = 0.f, s3 = 0.f;
#pragma unroll 4
    for (int k = 0; k < NH; k += 4) {
        s0 += h[b * NH + k + 0] * Wo[(size_t)(k + 0) * NDOUT + n];
        s1 += h[b * NH + k + 1] * Wo[(size_t)(k + 1) * NDOUT + n];
        s2 += h[b * NH + k + 2] * Wo[(size_t)(k + 2) * NDOUT + n];
        s3 += h[b * NH + k + 3] * Wo[(size_t)(k + 3) * NDOUT + n];
    }
    out[idx] = tanhf((s0 + s1) + (s2 + s3) + bo[n]);
}

// ---------------------------------------------------------------------------
extern "C" void kernel_launch(void* const* d_in, const int* in_sizes, int n_in,
                              void* d_out, int out_size) {
    const float* x  = (const float*)d_in[0];
    const float* Wi = (const float*)d_in[1];
    const float* bi = (const float*)d_in[2];
    const float* W0 = (const float*)d_in[3];
    const float* U0 = (const float*)d_in[4];
    const float* b0 = (const float*)d_in[5];
    const float* W1 = (const float*)d_in[6];
    const float* U1 = (const float*)d_in[7];
    const float* b1 = (const float*)d_in[8];
    const float* Wo = (const float*)d_in[9];
    const float* bo = (const float*)d_in[10];
    float* out = (float*)d_out;
    (void)in_sizes; (void)n_in; (void)out_size;

    k_init<<<512, 256>>>();
    k_xin<<<dim3(16, 512), 256>>>(x, Wi, bi);
    k_p0<<<dim3(64, 256), 256>>>(W0, b0);
    k_rnn<<<NBLK, 256>>>(U0, W1, U1, b1);
    k_out<<<32, 256>>>(Wo, bo, out);
}